// round 1
// baseline (speedup 1.0000x reference)
#include <cuda_runtime.h>
#include <cstdint>

// Problem constants
#define B_DIM  32768
#define IN_DIM 1024
#define U_DIM  1024
#define E_DIM  8

// Tiling
#define BM 128
#define BN 128
#define BK 32
#define THREADS 256
#define N_CHUNKS (E_DIM * IN_DIM / BK)   // 256

// Smem pads (uint32 elements)
#define AP (BK + 4)    // 36: A-frag LDS conflict-free ((4g+tg) distinct mod 32)
#define BP (BN + 4)    // 132: B-frag LDS 2-way worst

__device__ __forceinline__ uint32_t f2tf32(float f) {
    uint32_t r;
    asm("cvt.rna.tf32.f32 %0, %1;" : "=r"(r) : "f"(f));
    return r;
}

__device__ __forceinline__ void mma_tf32(float c[4], const uint32_t a[4],
                                         uint32_t b0, uint32_t b1) {
    asm volatile(
        "mma.sync.aligned.m16n8k8.row.col.f32.tf32.tf32.f32 "
        "{%0,%1,%2,%3}, {%4,%5,%6,%7}, {%8,%9}, {%0,%1,%2,%3};\n"
        : "+f"(c[0]), "+f"(c[1]), "+f"(c[2]), "+f"(c[3])
        : "r"(a[0]), "r"(a[1]), "r"(a[2]), "r"(a[3]), "r"(b0), "r"(b1));
}

__global__ __launch_bounds__(THREADS, 2)
void dense_expert_kernel(const float* __restrict__ x,
                         const float* __restrict__ gate,
                         const float* __restrict__ alpha,
                         const float* __restrict__ beta,
                         float* __restrict__ out)
{
    __shared__ uint32_t As[BM][AP];          // tf32 bits, [m][k]
    __shared__ uint32_t Bs[BK][BP];          // tf32 bits, [k][n]
    __shared__ float gate_sh[BM * E_DIM];    // [row][e]
    __shared__ float beta_sh[E_DIM * BN];    // [e][col]

    const int tid     = threadIdx.x;
    const int ubase   = blockIdx.x * BN;     // u-tile (fastest -> x L2 reuse)
    const int rowbase = blockIdx.y * BM;

    // Preload gate rows (128x8) and beta cols (8x128) — consumed after first barrier.
    {
        const int idx = tid * 4;
        float4 gv = *reinterpret_cast<const float4*>(gate + (size_t)rowbase * E_DIM + idx);
        *reinterpret_cast<float4*>(gate_sh + idx) = gv;
        const int e = idx >> 7;
        const int c = idx & 127;
        float4 bv = *reinterpret_cast<const float4*>(beta + (size_t)e * U_DIM + ubase + c);
        *reinterpret_cast<float4*>(beta_sh + idx) = bv;
    }

    const int lane   = tid & 31;
    const int warp   = tid >> 5;
    const int warp_m = warp & 3;     // 4 warps over m (32 rows each)
    const int warp_n = warp >> 2;    // 2 warps over n (64 cols each)
    const int g  = lane >> 2;        // groupID
    const int tg = lane & 3;         // threadID_in_group

    float acc[2][8][4];
#pragma unroll
    for (int i = 0; i < 2; ++i)
#pragma unroll
        for (int j = 0; j < 8; ++j)
#pragma unroll
            for (int k = 0; k < 4; ++k) acc[i][j][k] = 0.f;

    // A-tile staging coords: row = tid>>3 (+32j), col4 = tid&7  -> coalesced 128B rows
    const int a_row = tid >> 3;
    const int a_col = (tid & 7) * 4;
    // B-tile staging coords: row = tid>>5 (+8j), col4 = tid&31  -> coalesced 512B rows
    const int b_row = tid >> 5;
    const int b_col = (tid & 31) * 4;

    for (int chunk = 0; chunk < N_CHUNKS; ++chunk) {
        const int e  = chunk >> 5;          // 32 k-chunks per expert
        const int kc = (chunk & 31) * BK;

        // Prefetch gmem into registers (overlaps with previous chunk's MMA)
        float4 a_ld[4], b_ld[4];
#pragma unroll
        for (int j = 0; j < 4; ++j) {
            const int row = a_row + j * 32;
            a_ld[j] = *reinterpret_cast<const float4*>(
                x + (size_t)(rowbase + row) * IN_DIM + kc + a_col);
        }
#pragma unroll
        for (int j = 0; j < 4; ++j) {
            const int row = b_row + j * 8;
            b_ld[j] = *reinterpret_cast<const float4*>(
                alpha + (size_t)e * (IN_DIM * U_DIM) + (size_t)(kc + row) * U_DIM + ubase + b_col);
        }

        __syncthreads();   // prior compute done before smem overwrite

        // Stage A: scale by gate[row,e], convert to tf32
#pragma unroll
        for (int j = 0; j < 4; ++j) {
            const int row = a_row + j * 32;
            const float gs = gate_sh[row * E_DIM + e];
            As[row][a_col + 0] = f2tf32(a_ld[j].x * gs);
            As[row][a_col + 1] = f2tf32(a_ld[j].y * gs);
            As[row][a_col + 2] = f2tf32(a_ld[j].z * gs);
            As[row][a_col + 3] = f2tf32(a_ld[j].w * gs);
        }
        // Stage B: convert to tf32
#pragma unroll
        for (int j = 0; j < 4; ++j) {
            const int row = b_row + j * 8;
            Bs[row][b_col + 0] = f2tf32(b_ld[j].x);
            Bs[row][b_col + 1] = f2tf32(b_ld[j].y);
            Bs[row][b_col + 2] = f2tf32(b_ld[j].z);
            Bs[row][b_col + 3] = f2tf32(b_ld[j].w);
        }

        __syncthreads();

        // 4 k-steps of m16n8k8
#pragma unroll
        for (int ks = 0; ks < 4; ++ks) {
            const int kk = ks * 8;
            uint32_t afr[2][4];
#pragma unroll
            for (int mm = 0; mm < 2; ++mm) {
                const int m0 = warp_m * 32 + mm * 16;
                afr[mm][0] = As[m0 + g][kk + tg];
                afr[mm][1] = As[m0 + g + 8][kk + tg];
                afr[mm][2] = As[m0 + g][kk + tg + 4];
                afr[mm][3] = As[m0 + g + 8][kk + tg + 4];
            }
#pragma unroll
            for (int nn = 0; nn < 8; ++nn) {
                const int n0 = warp_n * 64 + nn * 8;
                const uint32_t b0 = Bs[kk + tg][n0 + g];
                const uint32_t b1 = Bs[kk + tg + 4][n0 + g];
                mma_tf32(acc[0][nn], afr[0], b0, b1);
                mma_tf32(acc[1][nn], afr[1], b0, b1);
            }
        }
    }

    // Epilogue: out = acc + sum_e gate[b,e]*beta[e,u]   (gate_sh/beta_sh untouched)
#pragma unroll
    for (int mm = 0; mm < 2; ++mm) {
        const int r0 = warp_m * 32 + mm * 16 + g;   // local rows
        const int r1 = r0 + 8;
        float ge0[E_DIM], ge1[E_DIM];
#pragma unroll
        for (int e = 0; e < E_DIM; ++e) {
            ge0[e] = gate_sh[r0 * E_DIM + e];
            ge1[e] = gate_sh[r1 * E_DIM + e];
        }
#pragma unroll
        for (int nn = 0; nn < 8; ++nn) {
            const int c = warp_n * 64 + nn * 8 + 2 * tg;  // local col (even)
            float b00 = 0.f, b01 = 0.f, b10 = 0.f, b11 = 0.f;
#pragma unroll
            for (int e = 0; e < E_DIM; ++e) {
                const float be0 = beta_sh[e * BN + c];
                const float be1 = beta_sh[e * BN + c + 1];
                b00 += ge0[e] * be0;  b01 += ge0[e] * be1;
                b10 += ge1[e] * be0;  b11 += ge1[e] * be1;
            }
            float2 v0 = make_float2(acc[mm][nn][0] + b00, acc[mm][nn][1] + b01);
            float2 v1 = make_float2(acc[mm][nn][2] + b10, acc[mm][nn][3] + b11);
            *reinterpret_cast<float2*>(out + (size_t)(rowbase + r0) * U_DIM + ubase + c) = v0;
            *reinterpret_cast<float2*>(out + (size_t)(rowbase + r1) * U_DIM + ubase + c) = v1;
        }
    }
}

extern "C" void kernel_launch(void* const* d_in, const int* in_sizes, int n_in,
                              void* d_out, int out_size)
{
    const float* x     = (const float*)d_in[0];
    const float* gate  = (const float*)d_in[1];
    const float* alpha = (const float*)d_in[2];
    const float* beta  = (const float*)d_in[3];
    float* out         = (float*)d_out;

    dim3 grid(U_DIM / BN, B_DIM / BM);   // (8, 256): u-tile fastest
    dense_expert_kernel<<<grid, THREADS>>>(x, gate, alpha, beta, out);
}

// round 4
// speedup vs baseline: 1.2838x; 1.2838x over previous
#include <cuda_runtime.h>
#include <cstdint>

#define B_DIM  32768
#define IN_DIM 1024
#define U_DIM  1024
#define E_DIM  8

#define BM 128
#define BN 128
#define BK 32
#define THREADS 256
#define NITER 256               // 32 kc * 8 e

// smem layout in floats
#define AROW 36                 // 32 + 4 pad: A frag LDS conflict-free
#define BROW 136                // 128 + 8 pad: B frag LDS conflict-free
#define A_STAGE_F (128 * AROW)  // 4608
#define B_STAGE_F (32 * BROW)   // 4352
#define OFF_GATE 0              // 128*8
#define OFF_BETA 1024           // 8*128
#define OFF_A    2048
#define OFF_B    (OFF_A + 2 * A_STAGE_F)        // 11264
#define SMEM_FLOATS (OFF_B + 3 * B_STAGE_F)     // 24320
#define SMEM_BYTES (SMEM_FLOATS * 4)            // 97280

__device__ float g_alphaR[(size_t)E_DIM * IN_DIM * U_DIM];   // rna-rounded alpha, same layout

__device__ __forceinline__ uint32_t smem_u32(const void* p) {
    uint32_t a;
    asm("{ .reg .u64 t; cvta.to.shared.u64 t, %1; cvt.u32.u64 %0, t; }" : "=r"(a) : "l"(p));
    return a;
}
__device__ __forceinline__ uint32_t f2tf32(float f) {
    uint32_t r; asm("cvt.rna.tf32.f32 %0, %1;" : "=r"(r) : "f"(f)); return r;
}
__device__ __forceinline__ void cp16(uint32_t dst, const void* src) {
    asm volatile("cp.async.cg.shared.global [%0], [%1], 16;" :: "r"(dst), "l"(src));
}
#define CP_COMMIT() asm volatile("cp.async.commit_group;" ::: "memory")
#define CP_WAIT1()  asm volatile("cp.async.wait_group 1;" ::: "memory")

__device__ __forceinline__ void mma_tf32(float c[4],
                                         uint32_t a0, uint32_t a1, uint32_t a2, uint32_t a3,
                                         uint32_t b0, uint32_t b1) {
    asm volatile(
        "mma.sync.aligned.m16n8k8.row.col.f32.tf32.tf32.f32 "
        "{%0,%1,%2,%3}, {%4,%5,%6,%7}, {%8,%9}, {%0,%1,%2,%3};\n"
        : "+f"(c[0]), "+f"(c[1]), "+f"(c[2]), "+f"(c[3])
        : "r"(a0), "r"(a1), "r"(a2), "r"(a3), "r"(b0), "r"(b1));
}

// ---------------- prologue: rna-round alpha into scratch ----------------
__global__ void round_alpha(const float* __restrict__ alpha) {
    const size_t idx = ((size_t)blockIdx.x * 256 + threadIdx.x) * 4;
    float4 v = *reinterpret_cast<const float4*>(alpha + idx);
    float4 r;
    r.x = __uint_as_float(f2tf32(v.x));
    r.y = __uint_as_float(f2tf32(v.y));
    r.z = __uint_as_float(f2tf32(v.z));
    r.w = __uint_as_float(f2tf32(v.w));
    *reinterpret_cast<float4*>(g_alphaR + idx) = r;
}

// ---------------- main kernel ----------------
__global__ __launch_bounds__(THREADS, 1)
void moe_kernel(const float* __restrict__ x,
                const float* __restrict__ gate,
                const float* __restrict__ beta,
                float* __restrict__ out)
{
    extern __shared__ float sm[];
    float* gate_sh = sm + OFF_GATE;
    float* beta_sh = sm + OFF_BETA;
    const uint32_t sbase = smem_u32(sm);
    const uint32_t aA = sbase + OFF_A * 4;
    const uint32_t aB = sbase + OFF_B * 4;

    const int tid  = threadIdx.x;
    const int wid  = tid >> 5;
    const int lane = tid & 31;
    const int warp_m = wid & 1;       // 2-way split over m (64 rows each)
    const int warp_n = wid >> 1;      // 4-way split over n (32 cols each)
    const int g  = lane >> 2;
    const int tg = lane & 3;
    const int mbase = blockIdx.y * BM;
    const int ubase = blockIdx.x * BN;

    // stage gate (128x8) and beta (8x128) tiles
    {
        const int idx = tid * 4;
        float4 gv = *reinterpret_cast<const float4*>(gate + (size_t)mbase * E_DIM + idx);
        *reinterpret_cast<float4*>(gate_sh + idx) = gv;
        const int e = idx >> 7, c = idx & 127;
        float4 bv = *reinterpret_cast<const float4*>(beta + (size_t)e * U_DIM + ubase + c);
        *reinterpret_cast<float4*>(beta_sh + idx) = bv;
    }

    // cp.async geometry
    const int a_row  = tid >> 1;          // 0..127
    const int a_half = (tid & 1) * 16;    // k offset
    const int b_k    = tid >> 3;          // 0..31
    const int b_c    = tid & 7;           // 16B chunk base

    auto issueA = [&](int kc) {
        const int st = kc & 1;
        const uint32_t dst = aA + st * (A_STAGE_F * 4) + a_row * (AROW * 4) + a_half * 4;
        const float* src = x + (size_t)(mbase + a_row) * IN_DIM + kc * BK + a_half;
#pragma unroll
        for (int j = 0; j < 4; ++j) cp16(dst + j * 16, src + j * 4);
    };
    auto issueB = [&](int it) {
        const int st = it % 3;
        const int kc = it >> 3, e = it & 7;
        const uint32_t dst = aB + st * (B_STAGE_F * 4) + b_k * (BROW * 4) + b_c * 16;
        const float* src = g_alphaR + (size_t)e * (IN_DIM * U_DIM)
                         + (size_t)(kc * BK + b_k) * U_DIM + ubase + b_c * 4;
#pragma unroll
        for (int j = 0; j < 4; ++j) cp16(dst + j * 128, src + j * 32);
    };

    // prologue: groups for iters 0 and 1
    issueA(0); issueB(0); CP_COMMIT();
    issueB(1);            CP_COMMIT();
    CP_WAIT1();
    __syncthreads();

    float Ar[4][4][4];     // [ks][mm][frag] unscaled x fragments, cached per kc
    float acc[4][4][4];    // [mm][nn][frag]
#pragma unroll
    for (int i = 0; i < 4; ++i)
#pragma unroll
        for (int j = 0; j < 4; ++j)
#pragma unroll
            for (int k = 0; k < 4; ++k) acc[i][j][k] = 0.f;

    for (int i = 0; i < NITER; ++i) {
        const int i2 = i + 2;
        if (i2 < NITER) {
            issueB(i2);
            if ((i2 & 7) == 0) issueA(i2 >> 3);
        }
        CP_COMMIT();

        const int kc = i >> 3, e = i & 7;
        const float* Bs = sm + OFF_B + (i % 3) * B_STAGE_F;

        if (e == 0) {
            const float* As = sm + OFF_A + (kc & 1) * A_STAGE_F;
#pragma unroll
            for (int ks = 0; ks < 4; ++ks)
#pragma unroll
                for (int mm = 0; mm < 4; ++mm) {
                    const int r0 = warp_m * 64 + mm * 16 + g;
                    const int k0 = ks * 8 + tg;
                    Ar[ks][mm][0] = As[r0 * AROW + k0];
                    Ar[ks][mm][1] = As[(r0 + 8) * AROW + k0];
                    Ar[ks][mm][2] = As[r0 * AROW + k0 + 4];
                    Ar[ks][mm][3] = As[(r0 + 8) * AROW + k0 + 4];
                }
        }

        // per-expert gate scales for this lane's rows
        float gs0[4], gs1[4];
#pragma unroll
        for (int mm = 0; mm < 4; ++mm) {
            const int r0 = warp_m * 64 + mm * 16 + g;
            gs0[mm] = gate_sh[r0 * E_DIM + e];
            gs1[mm] = gate_sh[(r0 + 8) * E_DIM + e];
        }

#pragma unroll
        for (int ks = 0; ks < 4; ++ks) {
            uint32_t b0[4], b1[4];
#pragma unroll
            for (int nn = 0; nn < 4; ++nn) {
                const int n = warp_n * 32 + nn * 8 + g;
                const int k = ks * 8 + tg;
                b0[nn] = __float_as_uint(Bs[k * BROW + n]);
                b1[nn] = __float_as_uint(Bs[(k + 4) * BROW + n]);
            }
#pragma unroll
            for (int mm = 0; mm < 4; ++mm) {
                const uint32_t a0 = __float_as_uint(Ar[ks][mm][0] * gs0[mm]);
                const uint32_t a1 = __float_as_uint(Ar[ks][mm][1] * gs1[mm]);
                const uint32_t a2 = __float_as_uint(Ar[ks][mm][2] * gs0[mm]);
                const uint32_t a3 = __float_as_uint(Ar[ks][mm][3] * gs1[mm]);
#pragma unroll
                for (int nn = 0; nn < 4; ++nn)
                    mma_tf32(acc[mm][nn], a0, a1, a2, a3, b0[nn], b1[nn]);
            }
        }

        CP_WAIT1();
        __syncthreads();
    }

    // epilogue: out = acc + sum_e gate[b,e] * beta[e,u]
#pragma unroll
    for (int mm = 0; mm < 4; ++mm) {
        const int row0 = warp_m * 64 + mm * 16 + g;
        const int row1 = row0 + 8;
        float ge0[E_DIM], ge1[E_DIM];
#pragma unroll
        for (int e = 0; e < E_DIM; ++e) {
            ge0[e] = gate_sh[row0 * E_DIM + e];
            ge1[e] = gate_sh[row1 * E_DIM + e];
        }
#pragma unroll
        for (int nn = 0; nn < 4; ++nn) {
            const int c = warp_n * 32 + nn * 8 + 2 * tg;
            float b00 = 0.f, b01 = 0.f, b10 = 0.f, b11 = 0.f;
#pragma unroll
            for (int e = 0; e < E_DIM; ++e) {
                const float be0 = beta_sh[e * BN + c];
                const float be1 = beta_sh[e * BN + c + 1];
                b00 += ge0[e] * be0;  b01 += ge0[e] * be1;
                b10 += ge1[e] * be0;  b11 += ge1[e] * be1;
            }
            float2 v0 = make_float2(acc[mm][nn][0] + b00, acc[mm][nn][1] + b01);
            float2 v1 = make_float2(acc[mm][nn][2] + b10, acc[mm][nn][3] + b11);
            *reinterpret_cast<float2*>(out + (size_t)(mbase + row0) * U_DIM + ubase + c) = v0;
            *reinterpret_cast<float2*>(out + (size_t)(mbase + row1) * U_DIM + ubase + c) = v1;
        }
    }
}

extern "C" void kernel_launch(void* const* d_in, const int* in_sizes, int n_in,
                              void* d_out, int out_size)
{
    const float* x     = (const float*)d_in[0];
    const float* gate  = (const float*)d_in[1];
    const float* alpha = (const float*)d_in[2];
    const float* beta  = (const float*)d_in[3];
    float* out         = (float*)d_out;

    round_alpha<<<(E_DIM * IN_DIM * U_DIM) / (256 * 4), 256>>>(alpha);

    static bool attr_set = false;
    if (!attr_set) {
        cudaFuncSetAttribute(moe_kernel, cudaFuncAttributeMaxDynamicSharedMemorySize, SMEM_BYTES);
        attr_set = true;
    }
    moe_kernel<<<dim3(U_DIM / BN, B_DIM / BM), THREADS, SMEM_BYTES>>>(x, gate, beta, out);
}